// round 1
// baseline (speedup 1.0000x reference)
#include <cuda_runtime.h>
#include <cstdint>

// MaskedNormalize: x [16, 4, 1024, 1024] fp32
// valid = (x != 0); per-batch masked mean/var (unbiased); out = valid ? (x-mean)/(sqrt(var)+eps) : 0
// Since invalid entries are exactly 0: sum(x*v)=sum(x), sum(x^2*v)=sum(x^2).

#define BATCHES    16
#define PER_BATCH  (4u * 1024u * 1024u)   // elements per batch
#define VEC_PER_B  (PER_BATCH / 4u)       // float4 per batch = 1,048,576

#define RBPB       128                    // reduction blocks per batch
#define RTHREADS   256
#define VEC_PER_RBLK (VEC_PER_B / RBPB)   // 8192 float4 per reduction block

#define NBPB       64                     // normalize blocks per batch
#define NTHREADS   256

#define EPS        1e-5f

// Deterministic scratch: every slot written every launch (no zeroing needed).
__device__ float  g_s1[BATCHES * RBPB];
__device__ float  g_s2[BATCHES * RBPB];
__device__ float  g_cn[BATCHES * RBPB];
__device__ float2 g_stats[BATCHES];       // {mean, rstd}

// ---------------------------------------------------------------------------
// Kernel 1: per-block partial sums (S1, S2, count) over contiguous chunks.
// Grid: (RBPB, BATCHES), RTHREADS threads.
// ---------------------------------------------------------------------------
__global__ __launch_bounds__(RTHREADS) void mn_reduce_kernel(const float* __restrict__ x)
{
    const int b   = blockIdx.y;
    const int blk = blockIdx.x;
    const float4* __restrict__ xb =
        reinterpret_cast<const float4*>(x + (size_t)b * PER_BATCH) + (size_t)blk * VEC_PER_RBLK;

    float s1 = 0.f, s2 = 0.f;
    int   cnt = 0;

    #pragma unroll 4
    for (unsigned j = threadIdx.x; j < VEC_PER_RBLK; j += RTHREADS) {
        float4 v = xb[j];
        s1 += (v.x + v.y) + (v.z + v.w);
        s2 += (v.x * v.x + v.y * v.y) + (v.z * v.z + v.w * v.w);
        cnt += (v.x != 0.f) + (v.y != 0.f) + (v.z != 0.f) + (v.w != 0.f);
    }

    // warp reduce
    #pragma unroll
    for (int off = 16; off > 0; off >>= 1) {
        s1  += __shfl_xor_sync(0xFFFFFFFFu, s1, off);
        s2  += __shfl_xor_sync(0xFFFFFFFFu, s2, off);
        cnt += __shfl_xor_sync(0xFFFFFFFFu, cnt, off);
    }

    __shared__ float sh1[RTHREADS / 32];
    __shared__ float sh2[RTHREADS / 32];
    __shared__ int   shc[RTHREADS / 32];
    const int lane = threadIdx.x & 31;
    const int wid  = threadIdx.x >> 5;
    if (lane == 0) { sh1[wid] = s1; sh2[wid] = s2; shc[wid] = cnt; }
    __syncthreads();

    if (wid == 0) {
        s1  = (lane < RTHREADS / 32) ? sh1[lane] : 0.f;
        s2  = (lane < RTHREADS / 32) ? sh2[lane] : 0.f;
        cnt = (lane < RTHREADS / 32) ? shc[lane] : 0;
        #pragma unroll
        for (int off = 4; off > 0; off >>= 1) {
            s1  += __shfl_xor_sync(0xFFFFFFFFu, s1, off);
            s2  += __shfl_xor_sync(0xFFFFFFFFu, s2, off);
            cnt += __shfl_xor_sync(0xFFFFFFFFu, cnt, off);
        }
        if (lane == 0) {
            g_s1[b * RBPB + blk] = s1;
            g_s2[b * RBPB + blk] = s2;
            g_cn[b * RBPB + blk] = (float)cnt;
        }
    }
}

// ---------------------------------------------------------------------------
// Kernel 2: finalize stats. Grid: (BATCHES), RBPB threads. Double precision.
// ---------------------------------------------------------------------------
__global__ __launch_bounds__(RBPB) void mn_finalize_kernel()
{
    const int b = blockIdx.x;
    const int t = threadIdx.x;

    double s1 = (double)g_s1[b * RBPB + t];
    double s2 = (double)g_s2[b * RBPB + t];
    double cn = (double)g_cn[b * RBPB + t];

    __shared__ double d1[RBPB], d2[RBPB], dc[RBPB];
    d1[t] = s1; d2[t] = s2; dc[t] = cn;
    __syncthreads();

    for (int off = RBPB / 2; off > 0; off >>= 1) {
        if (t < off) {
            d1[t] += d1[t + off];
            d2[t] += d2[t + off];
            dc[t] += dc[t + off];
        }
        __syncthreads();
    }

    if (t == 0) {
        double S1 = d1[0], S2 = d2[0], n = dc[0];
        double mean = S1 / n;
        double var  = (S2 - S1 * S1 / n) / (n - 1.0);
        float  rstd = 1.0f / (sqrtf((float)var) + EPS);
        g_stats[b] = make_float2((float)mean, rstd);
    }
}

// ---------------------------------------------------------------------------
// Kernel 3: normalize. Grid: (NBPB, BATCHES), NTHREADS threads, float4 I/O.
// ---------------------------------------------------------------------------
__global__ __launch_bounds__(NTHREADS) void mn_normalize_kernel(const float* __restrict__ x,
                                                                float* __restrict__ out)
{
    const int b = blockIdx.y;
    const float2 st = g_stats[b];
    const float mean = st.x, rstd = st.y;

    const float4* __restrict__ xb =
        reinterpret_cast<const float4*>(x + (size_t)b * PER_BATCH);
    float4* __restrict__ ob =
        reinterpret_cast<float4*>(out + (size_t)b * PER_BATCH);

    for (unsigned j = blockIdx.x * NTHREADS + threadIdx.x; j < VEC_PER_B;
         j += NBPB * NTHREADS) {
        float4 v = xb[j];
        float4 o;
        o.x = (v.x != 0.f) ? (v.x - mean) * rstd : 0.f;
        o.y = (v.y != 0.f) ? (v.y - mean) * rstd : 0.f;
        o.z = (v.z != 0.f) ? (v.z - mean) * rstd : 0.f;
        o.w = (v.w != 0.f) ? (v.w - mean) * rstd : 0.f;
        ob[j] = o;
    }
}

// ---------------------------------------------------------------------------
extern "C" void kernel_launch(void* const* d_in, const int* in_sizes, int n_in,
                              void* d_out, int out_size)
{
    const float* x   = (const float*)d_in[0];
    float*       out = (float*)d_out;

    dim3 rgrid(RBPB, BATCHES);
    mn_reduce_kernel<<<rgrid, RTHREADS>>>(x);

    mn_finalize_kernel<<<BATCHES, RBPB>>>();

    dim3 ngrid(NBPB, BATCHES);
    mn_normalize_kernel<<<ngrid, NTHREADS>>>(x, out);
}

// round 4
// speedup vs baseline: 1.0193x; 1.0193x over previous
#include <cuda_runtime.h>
#include <cstdint>

// MaskedNormalize fused single-kernel version.
// x [16, 4, 1024, 1024] fp32. valid = (x != 0).
// Since invalid entries are exactly 0: sum(x*v)=sum(x), sum(x^2*v)=sum(x^2);
// only the count needs the predicate.
//
// One persistent kernel: 128 blocks (8 per batch) x 1024 threads, all
// co-resident (128 <= 148 SMs). Phase 1: each block reduces its contiguous
// 2MB chunk -> partial (S1,S2,n) in fixed global slots. Software global
// barrier (monotonic arrival counter -- no reset needed: graph replays
// serialize, so arrivals partition into launches of exactly GRID each).
// Phase 2: each block computes its batch stats from 8 partials, then
// normalizes its own chunk in REVERSE order to hit the L2-resident tail
// it just read in phase 1.

#define BATCHES     16
#define PER_BATCH   (4u * 1024u * 1024u)      // elements per batch
#define VEC_PER_B   (PER_BATCH / 4u)          // float4 per batch = 1,048,576

#define BLKS_PER_B  8
#define GRID        (BATCHES * BLKS_PER_B)    // 128 blocks
#define THREADS     1024
#define CHUNK_F4    (VEC_PER_B / BLKS_PER_B)  // 131,072 float4 per block
#define ITERS       (CHUNK_F4 / THREADS)      // 128 iterations per thread

#define EPS         1e-5f

// Deterministic scratch: every slot written every launch.
__device__ float g_s1[GRID];
__device__ float g_s2[GRID];
__device__ float g_cn[GRID];
// Monotonic arrival counter; never reset (u64 cannot overflow in practice).
__device__ unsigned long long g_arrive = 0ULL;

__global__ __launch_bounds__(THREADS) void mn_fused_kernel(const float* __restrict__ x,
                                                           float* __restrict__ out)
{
    const int bid   = blockIdx.x;
    const int batch = bid / BLKS_PER_B;
    const int sub   = bid % BLKS_PER_B;

    const float4* __restrict__ xb =
        reinterpret_cast<const float4*>(x + (size_t)batch * PER_BATCH)
        + (size_t)sub * CHUNK_F4;
    float4* __restrict__ ob =
        reinterpret_cast<float4*>(out + (size_t)batch * PER_BATCH)
        + (size_t)sub * CHUNK_F4;

    // ---------------- Phase 1: partial sums over this block's chunk --------
    float s1 = 0.f, s2 = 0.f;
    int   cnt = 0;

    #pragma unroll 4
    for (unsigned j = threadIdx.x; j < CHUNK_F4; j += THREADS) {
        float4 v = xb[j];
        s1  += (v.x + v.y) + (v.z + v.w);
        s2  += (v.x * v.x + v.y * v.y) + (v.z * v.z + v.w * v.w);
        cnt += (v.x != 0.f) + (v.y != 0.f) + (v.z != 0.f) + (v.w != 0.f);
    }

    // warp reduce
    #pragma unroll
    for (int off = 16; off > 0; off >>= 1) {
        s1  += __shfl_xor_sync(0xFFFFFFFFu, s1, off);
        s2  += __shfl_xor_sync(0xFFFFFFFFu, s2, off);
        cnt += __shfl_xor_sync(0xFFFFFFFFu, cnt, off);
    }

    __shared__ float sh1[THREADS / 32];
    __shared__ float sh2[THREADS / 32];
    __shared__ int   shc[THREADS / 32];
    __shared__ float2 sh_stats;   // {mean, rstd} broadcast after barrier

    const int lane = threadIdx.x & 31;
    const int wid  = threadIdx.x >> 5;
    if (lane == 0) { sh1[wid] = s1; sh2[wid] = s2; shc[wid] = cnt; }
    __syncthreads();

    if (wid == 0) {
        s1  = (lane < THREADS / 32) ? sh1[lane] : 0.f;
        s2  = (lane < THREADS / 32) ? sh2[lane] : 0.f;
        cnt = (lane < THREADS / 32) ? shc[lane] : 0;
        #pragma unroll
        for (int off = 16; off > 0; off >>= 1) {
            s1  += __shfl_xor_sync(0xFFFFFFFFu, s1, off);
            s2  += __shfl_xor_sync(0xFFFFFFFFu, s2, off);
            cnt += __shfl_xor_sync(0xFFFFFFFFu, cnt, off);
        }
    }

    // ---------------- Global barrier + per-batch stats ---------------------
    if (threadIdx.x == 0) {
        // publish partials
        g_s1[bid] = s1;
        g_s2[bid] = s2;
        g_cn[bid] = (float)cnt;
        __threadfence();

        unsigned long long my = atomicAdd(&g_arrive, 1ULL);
        unsigned long long target = (my / GRID) * GRID + (unsigned long long)GRID;
        for (;;) {
            unsigned long long cur;
            asm volatile("ld.global.acquire.gpu.u64 %0, [%1];"
                         : "=l"(cur) : "l"(&g_arrive));
            if (cur >= target) break;
        }

        // All partials visible now; compute this batch's stats in double.
        double S1 = 0.0, S2 = 0.0, n = 0.0;
        #pragma unroll
        for (int k = 0; k < BLKS_PER_B; k++) {
            S1 += (double)g_s1[batch * BLKS_PER_B + k];
            S2 += (double)g_s2[batch * BLKS_PER_B + k];
            n  += (double)g_cn[batch * BLKS_PER_B + k];
        }
        double mean = S1 / n;
        double var  = (S2 - S1 * S1 / n) / (n - 1.0);
        float  rstd = 1.0f / (sqrtf((float)var) + EPS);
        sh_stats = make_float2((float)mean, rstd);
    }
    __syncthreads();

    const float mean = sh_stats.x;
    const float rstd = sh_stats.y;

    // ---------------- Phase 2: normalize own chunk, REVERSE order ----------
    // The tail of this chunk was read most recently in phase 1 -> likely
    // still L2-resident; consume it before phase-2 misses evict it.
    #pragma unroll 2
    for (int i = ITERS - 1; i >= 0; --i) {
        unsigned j = (unsigned)i * THREADS + threadIdx.x;
        float4 v = xb[j];
        float4 o;
        o.x = (v.x != 0.f) ? (v.x - mean) * rstd : 0.f;
        o.y = (v.y != 0.f) ? (v.y - mean) * rstd : 0.f;
        o.z = (v.z != 0.f) ? (v.z - mean) * rstd : 0.f;
        o.w = (v.w != 0.f) ? (v.w - mean) * rstd : 0.f;
        ob[j] = o;
    }
}

extern "C" void kernel_launch(void* const* d_in, const int* in_sizes, int n_in,
                              void* d_out, int out_size)
{
    const float* x   = (const float*)d_in[0];
    float*       out = (float*)d_out;
    mn_fused_kernel<<<GRID, THREADS>>>(x, out);
}